// round 15
// baseline (speedup 1.0000x reference)
#include <cuda_runtime.h>
#include <cuda_bf16.h>
#include <cstdint>

// ---------------------------------------------------------------------------
// Problem constants
//   B=8, T=2048, C=1024, NHEADS=16, HSIZE=64, N_GROUPS=8, group_t=256
//   qkv = x @ W_attn            [16384 x 3072], K=1024   (TF32 tensor cores)
//   per (b,h,g): causal attn over 257 tokens; rows<256 never see mean token
//   second attn over 7 groups (mean tokens), d=64 (fp32)
//   out = xo @ W_proj           [16384 x 1024], K=1024   (TF32 tensor cores)
// Outputs packed: out (16777216) | yq (57344) | yk (57344) | yv (57344)
//
// R12 change: all GEMM operands pre-truncated to tf32 once (x/W_attn/W_proj
// via a pass; xo at the attention epilogue) so the GEMM inner loop has zero
// cvt instructions: 96 LDS + 64 MMA per BK=32 tile instead of 96+96+64.
// ---------------------------------------------------------------------------

#define MTOT   16384          // B*T
#define CDIM   1024
#define QKVN   3072
#define GT     256
#define NBHG   1024           // 8*16*8
#define NMEAN  65536          // 8*16*8*64

__device__ float g_qkv[(size_t)MTOT * QKVN];   // 192 MB
__device__ float g_xo [(size_t)MTOT * CDIM];   //  64 MB (tf32-truncated)
__device__ float g_xt [(size_t)MTOT * CDIM];   //  64 MB (x, tf32-truncated)
__device__ float g_wat[(size_t)CDIM * QKVN];   //  12 MB (W_attn, tf32)
__device__ float g_wpt[(size_t)CDIM * CDIM];   //   4 MB (W_proj, tf32)
__device__ float g_qm [NMEAN];
__device__ float g_km [NMEAN];
__device__ float g_vm [NMEAN];
__device__ float g_xm [NMEAN];                 // attn output at mean-token rows

__device__ __forceinline__ uint32_t f2tf32(float f)
{
    uint32_t r;
    asm("cvt.rna.tf32.f32 %0, %1;" : "=r"(r) : "f"(f));
    return r;
}

// 2^z for z <= 0, FFMA-only (no MUFU). |rel err| < ~2e-7.
__device__ __forceinline__ float ex2p(float z)
{
    z = fmaxf(z, -100.f);
    float t = z + 12582912.f;                      // round-to-nearest int
    int   n = __float_as_int(t) - 0x4B400000;
    float f = z - (t - 12582912.f);                // f in [-0.5, 0.5]
    float p = 0.0013333558f;
    p = fmaf(p, f, 0.0096181291f);
    p = fmaf(p, f, 0.0555041087f);
    p = fmaf(p, f, 0.2402265069f);
    p = fmaf(p, f, 0.6931471806f);
    p = fmaf(p, f, 1.0f);
    return __int_as_float(__float_as_int(p) + (n << 23));
}

__device__ __forceinline__ void mma_tf32(float* c, const uint32_t* a,
                                         uint32_t b0, uint32_t b1)
{
    asm volatile(
        "mma.sync.aligned.m16n8k8.row.col.f32.tf32.tf32.f32 "
        "{%0,%1,%2,%3}, {%4,%5,%6,%7}, {%8,%9}, {%0,%1,%2,%3};"
        : "+f"(c[0]), "+f"(c[1]), "+f"(c[2]), "+f"(c[3])
        : "r"(a[0]), "r"(a[1]), "r"(a[2]), "r"(a[3]), "r"(b0), "r"(b1));
}

// ---------------------------------------------------------------------------
// Elementwise tf32 truncation: out[i] = tf32(in[i]). n % 4 == 0.
// ---------------------------------------------------------------------------
__global__ void trunc_tf32(const float* __restrict__ in,
                           float* __restrict__ out, int n)
{
    int i = (blockIdx.x * blockDim.x + threadIdx.x) * 4;
    if (i >= n) return;
    float4 v = *(const float4*)(in + i);
    v.x = __uint_as_float(f2tf32(v.x));
    v.y = __uint_as_float(f2tf32(v.y));
    v.z = __uint_as_float(f2tf32(v.z));
    v.w = __uint_as_float(f2tf32(v.w));
    *(float4*)(out + i) = v;
}

// ---------------------------------------------------------------------------
// TF32 tensor-core GEMM: 128x128 block, BK=32, 8 warps, cp.async 2-stage.
// Operands MUST already be tf32-truncated; inner loop is LDS+MMA only.
// ---------------------------------------------------------------------------
#define AS_STAGE 4608   // 128*36
#define BS_STAGE 4352   // 32*136
#define GEMM_SMEM ((2*(AS_STAGE + BS_STAGE)) * (int)sizeof(float))  // 71680 B

__global__ __launch_bounds__(256)
void gemm_tf32(const float* __restrict__ A, const float* __restrict__ B,
               float* __restrict__ C, int M, int N, int K)
{
    extern __shared__ float smem[];
    float* As = smem;
    float* Bs = smem + 2 * AS_STAGE;

    const int tid  = threadIdx.x;
    const int lane = tid & 31;
    const int w    = tid >> 5;
    const int wm0  = (w >> 1) * 32;
    const int wn0  = (w & 1) * 64;
    const int row0 = blockIdx.y * 128;
    const int col0 = blockIdx.x * 128;
    const int r  = lane >> 2;
    const int cq = lane & 3;

    float acc[2][8][4];
#pragma unroll
    for (int mt = 0; mt < 2; mt++)
#pragma unroll
        for (int nt = 0; nt < 8; nt++)
#pragma unroll
            for (int q = 0; q < 4; q++) acc[mt][nt][q] = 0.f;

    const int nk = K >> 5;

    auto prefetch = [&](int t, int s) {
        const float* Ab = A + (size_t)row0 * K + t * 32;
        const float* Bb = B + (size_t)(t * 32) * N + col0;
        float* as = As + s * AS_STAGE;
        float* bs = Bs + s * BS_STAGE;
#pragma unroll
        for (int i = 0; i < 4; i++) {
            int idx4 = tid + i * 256;
            int m  = idx4 >> 3, k4 = idx4 & 7;
            uint32_t da = (uint32_t)__cvta_generic_to_shared(as + m * 36 + k4 * 4);
            const float* sa = Ab + (size_t)m * K + k4 * 4;
            asm volatile("cp.async.cg.shared.global [%0], [%1], 16;" :: "r"(da), "l"(sa));
            int kb = idx4 >> 5, n4 = idx4 & 31;
            uint32_t db = (uint32_t)__cvta_generic_to_shared(bs + kb * 136 + n4 * 4);
            const float* sb = Bb + (size_t)kb * N + n4 * 4;
            asm volatile("cp.async.cg.shared.global [%0], [%1], 16;" :: "r"(db), "l"(sb));
        }
        asm volatile("cp.async.commit_group;");
    };

    prefetch(0, 0);

    for (int t = 0; t < nk; t++) {
        asm volatile("cp.async.wait_group 0;");
        __syncthreads();
        if (t + 1 < nk) prefetch(t + 1, (t + 1) & 1);

        const uint32_t* as = (const uint32_t*)(As + (t & 1) * AS_STAGE);
        const uint32_t* bs = (const uint32_t*)(Bs + (t & 1) * BS_STAGE);

#pragma unroll
        for (int kk = 0; kk < 4; kk++) {
            const int k = kk * 8;
            uint32_t af[2][4], bf[8][2];
#pragma unroll
            for (int mt = 0; mt < 2; mt++) {
                const uint32_t* ap = as + (wm0 + mt * 16 + r) * 36 + k + cq;
                af[mt][0] = ap[0];
                af[mt][1] = ap[8 * 36];
                af[mt][2] = ap[4];
                af[mt][3] = ap[8 * 36 + 4];
            }
#pragma unroll
            for (int nt = 0; nt < 8; nt++) {
                const uint32_t* bp = bs + (k + cq) * 136 + wn0 + nt * 8 + r;
                bf[nt][0] = bp[0];
                bf[nt][1] = bp[4 * 136];
            }
#pragma unroll
            for (int mt = 0; mt < 2; mt++)
#pragma unroll
                for (int nt = 0; nt < 8; nt++)
                    mma_tf32(acc[mt][nt], af[mt], bf[nt][0], bf[nt][1]);
        }
        __syncthreads();
    }

#pragma unroll
    for (int mt = 0; mt < 2; mt++) {
        const int rb = row0 + wm0 + mt * 16 + r;
#pragma unroll
        for (int nt = 0; nt < 8; nt++) {
            const int cb = col0 + wn0 + nt * 8 + cq * 2;
            *(float2*)(C + (size_t)rb * N + cb) =
                make_float2(acc[mt][nt][0], acc[mt][nt][1]);
            *(float2*)(C + (size_t)(rb + 8) * N + cb) =
                make_float2(acc[mt][nt][2], acc[mt][nt][3]);
        }
    }
}

// ---------------------------------------------------------------------------
// Per-(b,h,g,d) means of q/k/v over the 256 positions of the group.
// ---------------------------------------------------------------------------
__global__ void mean_kernel()
{
    int idx = blockIdx.x * blockDim.x + threadIdx.x;
    if (idx >= NMEAN) return;
    int d = idx & 63;
    int g = (idx >> 6) & 7;
    int h = (idx >> 9) & 15;
    int b = idx >> 13;
    const float* base = g_qkv + ((size_t)(b * 2048 + g * GT)) * QKVN + h * 64 + d;
    float sq = 0.f, sk = 0.f, sv = 0.f;
    for (int p = 0; p < GT; p++) {
        size_t o = (size_t)p * QKVN;
        sq += base[o];
        sk += base[o + 1024];
        sv += base[o + 2048];
    }
    const float inv = 1.f / 256.f;
    g_qm[idx] = sq * inv;
    g_km[idx] = sk * inv;
    g_vm[idx] = sv * inv;
}

// ---------------------------------------------------------------------------
// Group attention (tensor-core): one block per (b,h,g), 288 threads.
// Epilogue writes g_xo tf32-truncated (identical numerics to converting at
// the proj-GEMM fragment load).
// ---------------------------------------------------------------------------
#define KSTR 68
#define ATTN_SMEM_F (2 * 257 * KSTR + 8 * 16 * 36 + 64)   // 39624 floats
#define L2E 1.4426950408889634f

__global__ __launch_bounds__(288)
void attn_group_mma()
{
    extern __shared__ float sm[];
    float* Ks = sm;                       // 257*68 (tf32-truncated values)
    float* Vs = sm + 257 * KSTR;          // 257*68 (fp32)
    float* Ps = sm + 2 * 257 * KSTR;      // 8 * 576
    float* Qm = Ps + 8 * 576;             // 64

    const int bhg  = blockIdx.x;
    const int g    = bhg & 7;
    const int h    = (bhg >> 3) & 15;
    const int b    = bhg >> 7;
    const int tid  = threadIdx.x;
    const int lane = tid & 31;
    const int w    = tid >> 5;
    const int brow = b * 2048 + g * GT;
    const float* qkvb = g_qkv + (size_t)brow * QKVN + h * 64;

    for (int idx = tid; idx < GT * 64; idx += 288) {
        int p = idx >> 6, d = idx & 63;
        const float* src = qkvb + (size_t)p * QKVN + d;
        Ks[p * KSTR + d] = __uint_as_float(f2tf32(src[1024]));
        Vs[p * KSTR + d] = src[2048];
    }
    if (tid < 64) {
        Ks[256 * KSTR + tid] = __uint_as_float(f2tf32(g_km[bhg * 64 + tid]));
        Vs[256 * KSTR + tid] = g_vm[bhg * 64 + tid];
        Qm[tid] = g_qm[bhg * 64 + tid];
    }
    __syncthreads();

    const int r  = lane >> 2;
    const int cq = lane & 3;
    const float QS = 0.125f * L2E;        // scores in log2 units

    if (w < 8) {
        float* myP = Ps + w * 576;

        for (int half = 0; half < 2; half++) {
            const int tile = half ? (15 - w) : w;
            const int i0 = tile * 16;

            uint32_t qf[8][4];
            const float* qg = qkvb + (size_t)i0 * QKVN;
#pragma unroll
            for (int kc = 0; kc < 8; kc++) {
                qf[kc][0] = f2tf32(QS * qg[(size_t)r * QKVN + kc * 8 + cq]);
                qf[kc][1] = f2tf32(QS * qg[(size_t)(r + 8) * QKVN + kc * 8 + cq]);
                qf[kc][2] = f2tf32(QS * qg[(size_t)r * QKVN + kc * 8 + cq + 4]);
                qf[kc][3] = f2tf32(QS * qg[(size_t)(r + 8) * QKVN + kc * 8 + cq + 4]);
            }

            float m0 = -1e30f, m1 = -1e30f, l0 = 0.f, l1 = 0.f;
            float oacc[8][4];
#pragma unroll
            for (int nt = 0; nt < 8; nt++)
#pragma unroll
                for (int q = 0; q < 4; q++) oacc[nt][q] = 0.f;

            const int nch = (i0 + 15) / 32 + 1;
            for (int c = 0; c < nch; c++) {
                const int j0 = c * 32;

                float s[4][4];
#pragma unroll
                for (int nt = 0; nt < 4; nt++) {
                    s[nt][0] = s[nt][1] = s[nt][2] = s[nt][3] = 0.f;
                    const float* kb = Ks + (j0 + nt * 8 + r) * KSTR;
#pragma unroll
                    for (int kc = 0; kc < 8; kc++) {
                        uint32_t b0 = __float_as_uint(kb[kc * 8 + cq]);
                        uint32_t b1 = __float_as_uint(kb[kc * 8 + cq + 4]);
                        mma_tf32(s[nt], qf[kc], b0, b1);
                    }
                }

                if (j0 + 31 > i0) {
#pragma unroll
                    for (int nt = 0; nt < 4; nt++) {
                        int j = j0 + nt * 8 + 2 * cq;
                        if (j     > i0 + r)     s[nt][0] = -1e30f;
                        if (j + 1 > i0 + r)     s[nt][1] = -1e30f;
                        if (j     > i0 + r + 8) s[nt][2] = -1e30f;
                        if (j + 1 > i0 + r + 8) s[nt][3] = -1e30f;
                    }
                }

                float cm0 = -1e30f, cm1 = -1e30f;
#pragma unroll
                for (int nt = 0; nt < 4; nt++) {
                    cm0 = fmaxf(cm0, fmaxf(s[nt][0], s[nt][1]));
                    cm1 = fmaxf(cm1, fmaxf(s[nt][2], s[nt][3]));
                }
                cm0 = fmaxf(cm0, __shfl_xor_sync(0xffffffffu, cm0, 1));
                cm0 = fmaxf(cm0, __shfl_xor_sync(0xffffffffu, cm0, 2));
                cm1 = fmaxf(cm1, __shfl_xor_sync(0xffffffffu, cm1, 1));
                cm1 = fmaxf(cm1, __shfl_xor_sync(0xffffffffu, cm1, 2));
                float mn0 = fmaxf(m0, cm0), mn1 = fmaxf(m1, cm1);
                float a0 = ex2p(m0 - mn0), a1 = ex2p(m1 - mn1);
                m0 = mn0; m1 = mn1;
                l0 *= a0; l1 *= a1;
#pragma unroll
                for (int nt = 0; nt < 8; nt++) {
                    oacc[nt][0] *= a0; oacc[nt][1] *= a0;
                    oacc[nt][2] *= a1; oacc[nt][3] *= a1;
                }
#pragma unroll
                for (int nt = 0; nt < 4; nt++) {
                    float p0 = ex2p(s[nt][0] - m0), p1 = ex2p(s[nt][1] - m0);
                    float p2 = ex2p(s[nt][2] - m1), p3 = ex2p(s[nt][3] - m1);
                    l0 += p0 + p1; l1 += p2 + p3;
                    int jl = nt * 8 + 2 * cq;
                    myP[r * 36 + jl]           = p0;
                    myP[r * 36 + jl + 1]       = p1;
                    myP[(r + 8) * 36 + jl]     = p2;
                    myP[(r + 8) * 36 + jl + 1] = p3;
                }
                __syncwarp();

#pragma unroll
                for (int kc = 0; kc < 4; kc++) {
                    uint32_t af[4];
                    af[0] = f2tf32(myP[r * 36 + kc * 8 + cq]);
                    af[1] = f2tf32(myP[(r + 8) * 36 + kc * 8 + cq]);
                    af[2] = f2tf32(myP[r * 36 + kc * 8 + cq + 4]);
                    af[3] = f2tf32(myP[(r + 8) * 36 + kc * 8 + cq + 4]);
                    const float* vb0 = Vs + (j0 + kc * 8 + cq) * KSTR;
                    const float* vb1 = Vs + (j0 + kc * 8 + cq + 4) * KSTR;
#pragma unroll
                    for (int nt = 0; nt < 8; nt++) {
                        uint32_t b0 = f2tf32(vb0[nt * 8 + r]);
                        uint32_t b1 = f2tf32(vb1[nt * 8 + r]);
                        mma_tf32(oacc[nt], af, b0, b1);
                    }
                }
                __syncwarp();
            }

            l0 += __shfl_xor_sync(0xffffffffu, l0, 1);
            l0 += __shfl_xor_sync(0xffffffffu, l0, 2);
            l1 += __shfl_xor_sync(0xffffffffu, l1, 1);
            l1 += __shfl_xor_sync(0xffffffffu, l1, 2);
            float inv0 = 1.f / l0, inv1 = 1.f / l1;
            float* o0row = g_xo + (size_t)(brow + i0 + r) * CDIM + h * 64;
            float* o1row = g_xo + (size_t)(brow + i0 + r + 8) * CDIM + h * 64;
#pragma unroll
            for (int nt = 0; nt < 8; nt++) {
                *(float2*)(o0row + nt * 8 + 2 * cq) = make_float2(
                    __uint_as_float(f2tf32(oacc[nt][0] * inv0)),
                    __uint_as_float(f2tf32(oacc[nt][1] * inv0)));
                *(float2*)(o1row + nt * 8 + 2 * cq) = make_float2(
                    __uint_as_float(f2tf32(oacc[nt][2] * inv1)),
                    __uint_as_float(f2tf32(oacc[nt][3] * inv1)));
            }
        }
    } else {
        // ---- warp 8: mean-token row (i = 256 attends j = 0..256)
        float s[9];
#pragma unroll
        for (int t = 0; t < 9; t++) s[t] = 0.f;
#pragma unroll
        for (int d0 = 0; d0 < 64; d0 += 16) {
            float q[16];
#pragma unroll
            for (int dd = 0; dd < 16; dd++) q[dd] = Qm[d0 + dd];
#pragma unroll
            for (int t = 0; t < 9; t++) {
                int j = lane + 32 * t;
                if (j < 257) {
                    const float* kb = Ks + j * KSTR + d0;
#pragma unroll
                    for (int dd = 0; dd < 16; dd++) s[t] += q[dd] * kb[dd];
                }
            }
        }
        float m = -1e30f;
#pragma unroll
        for (int t = 0; t < 9; t++) {
            int j = lane + 32 * t;
            if (j < 257) { s[t] *= QS; m = fmaxf(m, s[t]); }
        }
#pragma unroll
        for (int off = 16; off; off >>= 1)
            m = fmaxf(m, __shfl_xor_sync(0xffffffffu, m, off));
        float p[9]; float sum = 0.f;
#pragma unroll
        for (int t = 0; t < 9; t++) {
            int j = lane + 32 * t;
            p[t] = (j < 257) ? ex2p(s[t] - m) : 0.f;
            sum += p[t];
        }
#pragma unroll
        for (int off = 16; off; off >>= 1)
            sum += __shfl_xor_sync(0xffffffffu, sum, off);
        const float inv = 1.f / sum;
        float o0 = 0.f, o1 = 0.f;
        for (int t = 0; t < 9; t++) {
            int jmax = (t < 8) ? 32 : 1;
            for (int jj = 0; jj < jmax; jj++) {
                int j = 32 * t + jj;
                float pj = __shfl_sync(0xffffffffu, p[t], jj);
                o0 += pj * Vs[j * KSTR + lane];
                o1 += pj * Vs[j * KSTR + lane + 32];
            }
        }
        g_xm[bhg * 64 + lane]      = o0 * inv;
        g_xm[bhg * 64 + lane + 32] = o1 * inv;
    }
}

// ---------------------------------------------------------------------------
// Second attention over 7 groups (mean tokens), per (b,h). Emits yq/yk/yv.
// ---------------------------------------------------------------------------
__global__ void attn_cross_kernel(float* __restrict__ yq,
                                  float* __restrict__ yk,
                                  float* __restrict__ yv)
{
    __shared__ float Q[7][64], K[7][64], V[7][64], S[7][8];
    const int bh  = blockIdx.x;
    const int tid = threadIdx.x;

    const float* qb = g_qm + bh * 8 * 64;
    const float* kb = g_km + bh * 8 * 64;
    const float* vb = g_xm + bh * 8 * 64;
    for (int i = 0; i < 7; i++) {
        Q[i][tid] = qb[i * 64 + tid];
        K[i][tid] = kb[i * 64 + tid];
        V[i][tid] = vb[i * 64 + tid];
    }
    __syncthreads();

    if (tid < 49) {
        int i = tid / 7, j = tid % 7;
        float s = 0.f;
#pragma unroll
        for (int d = 0; d < 64; d++) s += Q[i][d] * K[j][d];
        S[i][j] = s * 0.125f;
    }
    __syncthreads();

    for (int i = 0; i < 7; i++) {
        float m = -3.0e38f;
        for (int j = 0; j <= i; j++) m = fmaxf(m, S[i][j]);
        float p[7], sum = 0.f;
        for (int j = 0; j <= i; j++) { p[j] = __expf(S[i][j] - m); sum += p[j]; }
        float o = 0.f;
        for (int j = 0; j <= i; j++) o += p[j] * V[j][tid];
        yv[(bh * 7 + i) * 64 + tid] = o / sum;
        yq[(bh * 7 + i) * 64 + tid] = Q[i][tid];
        yk[(bh * 7 + i) * 64 + tid] = K[i][tid];
    }
}

// ---------------------------------------------------------------------------
// kernel_launch
// ---------------------------------------------------------------------------
extern "C" void kernel_launch(void* const* d_in, const int* in_sizes, int n_in,
                              void* d_out, int out_size)
{
    const float* x      = (const float*)d_in[0];
    const float* W_attn = (const float*)d_in[1];
    const float* W_proj = (const float*)d_in[2];

    float* out = (float*)d_out;
    float* yq  = out + (size_t)MTOT * CDIM;
    float* yk  = yq + 8 * 16 * 7 * 64;
    float* yv  = yk + 8 * 16 * 7 * 64;

    float *qkv_p, *xo_p, *xt_p, *wat_p, *wpt_p;
    cudaGetSymbolAddress((void**)&qkv_p, g_qkv);
    cudaGetSymbolAddress((void**)&xo_p,  g_xo);
    cudaGetSymbolAddress((void**)&xt_p,  g_xt);
    cudaGetSymbolAddress((void**)&wat_p, g_wat);
    cudaGetSymbolAddress((void**)&wpt_p, g_wpt);

    const int ATTN_SMEM = ATTN_SMEM_F * (int)sizeof(float);   // 158,496 B
    cudaFuncSetAttribute(attn_group_mma,
                         cudaFuncAttributeMaxDynamicSharedMemorySize, ATTN_SMEM);
    cudaFuncSetAttribute(gemm_tf32,
                         cudaFuncAttributeMaxDynamicSharedMemorySize, GEMM_SMEM);

    // 0) tf32-truncate GEMM operands (one elementwise pass each)
    trunc_tf32<<<(MTOT * CDIM / 4 + 255) / 256, 256>>>(x, xt_p, MTOT * CDIM);
    trunc_tf32<<<(CDIM * QKVN / 4 + 255) / 256, 256>>>(W_attn, wat_p, CDIM * QKVN);
    trunc_tf32<<<(CDIM * CDIM / 4 + 255) / 256, 256>>>(W_proj, wpt_p, CDIM * CDIM);

    // 1) qkv = x @ W_attn   (TF32 tensor cores, pre-truncated operands)
    gemm_tf32<<<dim3(QKVN / 128, MTOT / 128), 256, GEMM_SMEM>>>(
        xt_p, wat_p, qkv_p, MTOT, QKVN, CDIM);
    // 2) per-(b,h,g) means
    mean_kernel<<<NMEAN / 256, 256>>>();
    // 3) group attention (tensor cores) -> g_xo (tf32-truncated), g_xm
    attn_group_mma<<<NBHG, 288, ATTN_SMEM>>>();
    // 4) cross-group attention -> yq/yk/yv
    attn_cross_kernel<<<128, 64>>>(yq, yk, yv);
    // 5) out = xo @ W_proj  (TF32 tensor cores, pre-truncated operands)
    gemm_tf32<<<dim3(CDIM / 128, MTOT / 128), 256, GEMM_SMEM>>>(
        xo_p, wpt_p, out, MTOT, CDIM, CDIM);
}

// round 16
// speedup vs baseline: 1.3801x; 1.3801x over previous
#include <cuda_runtime.h>
#include <cuda_bf16.h>
#include <cstdint>

// ---------------------------------------------------------------------------
// Problem constants
//   B=8, T=2048, C=1024, NHEADS=16, HSIZE=64, N_GROUPS=8, group_t=256
//   qkv = x @ W_attn            [16384 x 3072], K=1024   (TF32 tensor cores)
//   per (b,h,g): causal attn over 257 tokens; rows<256 never see mean token
//   second attn over 7 groups (mean tokens), d=64 (fp32)
//   out = xo @ W_proj           [16384 x 1024], K=1024   (TF32 tensor cores)
// Outputs packed: out (16777216) | yq (57344) | yk (57344) | yv (57344)
//
// R16: revert R15 cvt-hoist (it regressed). GEMM fragment loads via
// ldmatrix.m8n8.x4.b16 (tf32 trick) with weights pre-transposed to [N,K]
// so both A and B tiles cp.async in row-major K-major form. CVTs stay
// in-loop (R15 showed the LDS->CVT->MMA chain schedules better).
// ---------------------------------------------------------------------------

#define MTOT   16384          // B*T
#define CDIM   1024
#define QKVN   3072
#define GT     256
#define NBHG   1024           // 8*16*8
#define NMEAN  65536          // 8*16*8*64

__device__ float g_qkv[(size_t)MTOT * QKVN];   // 192 MB
__device__ float g_xo [(size_t)MTOT * CDIM];   //  64 MB
__device__ float g_wat[(size_t)QKVN * CDIM];   //  12 MB (W_attn^T, [N,K])
__device__ float g_wpt[(size_t)CDIM * CDIM];   //   4 MB (W_proj^T, [N,K])
__device__ float g_qm [NMEAN];
__device__ float g_km [NMEAN];
__device__ float g_vm [NMEAN];
__device__ float g_xm [NMEAN];                 // attn output at mean-token rows

__device__ __forceinline__ uint32_t f2tf32(float f)
{
    uint32_t r;
    asm("cvt.rna.tf32.f32 %0, %1;" : "=r"(r) : "f"(f));
    return r;
}

// 2^z for z <= 0, FFMA-only (no MUFU). |rel err| < ~2e-7.
__device__ __forceinline__ float ex2p(float z)
{
    z = fmaxf(z, -100.f);
    float t = z + 12582912.f;                      // round-to-nearest int
    int   n = __float_as_int(t) - 0x4B400000;
    float f = z - (t - 12582912.f);                // f in [-0.5, 0.5]
    float p = 0.0013333558f;
    p = fmaf(p, f, 0.0096181291f);
    p = fmaf(p, f, 0.0555041087f);
    p = fmaf(p, f, 0.2402265069f);
    p = fmaf(p, f, 0.6931471806f);
    p = fmaf(p, f, 1.0f);
    return __int_as_float(__float_as_int(p) + (n << 23));
}

__device__ __forceinline__ void mma_tf32(float* c, const uint32_t* a,
                                         uint32_t b0, uint32_t b1)
{
    asm volatile(
        "mma.sync.aligned.m16n8k8.row.col.f32.tf32.tf32.f32 "
        "{%0,%1,%2,%3}, {%4,%5,%6,%7}, {%8,%9}, {%0,%1,%2,%3};"
        : "+f"(c[0]), "+f"(c[1]), "+f"(c[2]), "+f"(c[3])
        : "r"(a[0]), "r"(a[1]), "r"(a[2]), "r"(a[3]), "r"(b0), "r"(b1));
}

__device__ __forceinline__ void ldsm4(uint32_t& r0, uint32_t& r1,
                                      uint32_t& r2, uint32_t& r3, uint32_t addr)
{
    asm volatile("ldmatrix.sync.aligned.m8n8.x4.shared.b16 {%0,%1,%2,%3}, [%4];"
                 : "=r"(r0), "=r"(r1), "=r"(r2), "=r"(r3) : "r"(addr));
}

// ---------------------------------------------------------------------------
// Tiled transpose: out[C][R] = in[R][C]^T.  R,C multiples of 32.
// ---------------------------------------------------------------------------
__global__ void transpose_k(const float* __restrict__ in,
                            float* __restrict__ out, int R, int C)
{
    __shared__ float t[32][33];
    int x = blockIdx.x * 32 + threadIdx.x;
    int y = blockIdx.y * 32 + threadIdx.y;
#pragma unroll
    for (int j = 0; j < 32; j += 8)
        t[threadIdx.y + j][threadIdx.x] = in[(size_t)(y + j) * C + x];
    __syncthreads();
    int x2 = blockIdx.y * 32 + threadIdx.x;
    int y2 = blockIdx.x * 32 + threadIdx.y;
#pragma unroll
    for (int j = 0; j < 32; j += 8)
        out[(size_t)(y2 + j) * R + x2] = t[threadIdx.x][threadIdx.y + j];
}

// ---------------------------------------------------------------------------
// TF32 tensor-core GEMM: C[M,N] = A[M,K] @ Bt[N,K]^T.
// 128x128 block, BK=32, 8 warps (4x2), warp tile 32x64, cp.async 2-stage.
// Both smem tiles are [128 rows][36 floats] (144B stride); fragments loaded
// with ldmatrix.x4 (tf32-as-b16 trick), cvt to tf32 in-loop.
// ---------------------------------------------------------------------------
#define TSTAGE 4608   // 128*36 floats per stage (A and B identical)
#define GEMM_SMEM (4 * TSTAGE * (int)sizeof(float))  // 73728 B

__global__ __launch_bounds__(256)
void gemm_tf32(const float* __restrict__ A, const float* __restrict__ Bt,
               float* __restrict__ C, int M, int N, int K)
{
    extern __shared__ float smem[];
    // As stage s: smem + s*TSTAGE ; Bs stage s: smem + (2+s)*TSTAGE

    const int tid  = threadIdx.x;
    const int lane = tid & 31;
    const int w    = tid >> 5;
    const int wm0  = (w >> 1) * 32;
    const int wn0  = (w & 1) * 64;
    const int row0 = blockIdx.y * 128;
    const int col0 = blockIdx.x * 128;

    // ldmatrix lane addressing
    const int lrow = lane & 7;
    const int lg   = lane >> 3;          // 0..3 (tile group)

    // A groups: g&1 -> +8 rows, g>>1 -> +16B (k half)
    const int aoff0 = (wm0 + lrow + (lg & 1) * 8) * 144 + (lg >> 1) * 16;
    const int aoff1 = aoff0 + 16 * 144;
    // B groups: g>>1 -> +8 rows, g&1 -> +16B (k half); q covers n-tiles 2q,2q+1
    int boff[4];
#pragma unroll
    for (int q = 0; q < 4; q++)
        boff[q] = (wn0 + q * 16 + lrow + (lg >> 1) * 8) * 144 + (lg & 1) * 16;

    float acc[2][8][4];
#pragma unroll
    for (int mt = 0; mt < 2; mt++)
#pragma unroll
        for (int nt = 0; nt < 8; nt++)
#pragma unroll
            for (int q = 0; q < 4; q++) acc[mt][nt][q] = 0.f;

    const int nk = K >> 5;

    // prefetch tile t into stage s (A and B tiles are layout-identical)
    auto prefetch = [&](int t, int s) {
        const float* Ab = A  + (size_t)row0 * K + t * 32;
        const float* Bb = Bt + (size_t)col0 * K + t * 32;
        float* as = smem + s * TSTAGE;
        float* bs = smem + (2 + s) * TSTAGE;
#pragma unroll
        for (int i = 0; i < 4; i++) {
            int idx4 = tid + i * 256;            // 0..1023
            int m  = idx4 >> 3, k4 = idx4 & 7;   // 128 rows x 8 float4
            uint32_t da = (uint32_t)__cvta_generic_to_shared(as + m * 36 + k4 * 4);
            const float* sa = Ab + (size_t)m * K + k4 * 4;
            asm volatile("cp.async.cg.shared.global [%0], [%1], 16;" :: "r"(da), "l"(sa));
            uint32_t db = (uint32_t)__cvta_generic_to_shared(bs + m * 36 + k4 * 4);
            const float* sb = Bb + (size_t)m * K + k4 * 4;
            asm volatile("cp.async.cg.shared.global [%0], [%1], 16;" :: "r"(db), "l"(sb));
        }
        asm volatile("cp.async.commit_group;");
    };

    prefetch(0, 0);

    for (int t = 0; t < nk; t++) {
        asm volatile("cp.async.wait_group 0;");
        __syncthreads();
        if (t + 1 < nk) prefetch(t + 1, (t + 1) & 1);

        const uint32_t as_base =
            (uint32_t)__cvta_generic_to_shared(smem + (t & 1) * TSTAGE);
        const uint32_t bs_base =
            (uint32_t)__cvta_generic_to_shared(smem + (2 + (t & 1)) * TSTAGE);

#pragma unroll
        for (int kk = 0; kk < 4; kk++) {
            const int kb = kk * 32;   // byte offset of k-slice
            uint32_t ar[2][4], br[8][2];
            ldsm4(ar[0][0], ar[0][1], ar[0][2], ar[0][3], as_base + aoff0 + kb);
            ldsm4(ar[1][0], ar[1][1], ar[1][2], ar[1][3], as_base + aoff1 + kb);
#pragma unroll
            for (int q = 0; q < 4; q++) {
                uint32_t r0, r1, r2, r3;
                ldsm4(r0, r1, r2, r3, bs_base + boff[q] + kb);
                br[2 * q][0] = r0; br[2 * q][1] = r1;
                br[2 * q + 1][0] = r2; br[2 * q + 1][1] = r3;
            }

            uint32_t af[2][4], bf[8][2];
#pragma unroll
            for (int mt = 0; mt < 2; mt++)
#pragma unroll
                for (int i = 0; i < 4; i++)
                    af[mt][i] = f2tf32(__uint_as_float(ar[mt][i]));
#pragma unroll
            for (int nt = 0; nt < 8; nt++) {
                bf[nt][0] = f2tf32(__uint_as_float(br[nt][0]));
                bf[nt][1] = f2tf32(__uint_as_float(br[nt][1]));
            }

#pragma unroll
            for (int mt = 0; mt < 2; mt++)
#pragma unroll
                for (int nt = 0; nt < 8; nt++)
                    mma_tf32(acc[mt][nt], af[mt], bf[nt][0], bf[nt][1]);
        }
        __syncthreads();
    }

#pragma unroll
    for (int mt = 0; mt < 2; mt++) {
        const int r  = lane >> 2;
        const int cq = lane & 3;
        const int rb = row0 + wm0 + mt * 16 + r;
#pragma unroll
        for (int nt = 0; nt < 8; nt++) {
            const int cb = col0 + wn0 + nt * 8 + cq * 2;
            *(float2*)(C + (size_t)rb * N + cb) =
                make_float2(acc[mt][nt][0], acc[mt][nt][1]);
            *(float2*)(C + (size_t)(rb + 8) * N + cb) =
                make_float2(acc[mt][nt][2], acc[mt][nt][3]);
        }
    }
}

// ---------------------------------------------------------------------------
// Per-(b,h,g,d) means of q/k/v over the 256 positions of the group.
// ---------------------------------------------------------------------------
__global__ void mean_kernel()
{
    int idx = blockIdx.x * blockDim.x + threadIdx.x;
    if (idx >= NMEAN) return;
    int d = idx & 63;
    int g = (idx >> 6) & 7;
    int h = (idx >> 9) & 15;
    int b = idx >> 13;
    const float* base = g_qkv + ((size_t)(b * 2048 + g * GT)) * QKVN + h * 64 + d;
    float sq = 0.f, sk = 0.f, sv = 0.f;
    for (int p = 0; p < GT; p++) {
        size_t o = (size_t)p * QKVN;
        sq += base[o];
        sk += base[o + 1024];
        sv += base[o + 2048];
    }
    const float inv = 1.f / 256.f;
    g_qm[idx] = sq * inv;
    g_km[idx] = sk * inv;
    g_vm[idx] = sv * inv;
}

// ---------------------------------------------------------------------------
// Group attention (tensor-core): one block per (b,h,g), 288 threads.
// (identical to R11 best)
// ---------------------------------------------------------------------------
#define KSTR 68
#define ATTN_SMEM_F (2 * 257 * KSTR + 8 * 16 * 36 + 64)   // 39624 floats
#define L2E 1.4426950408889634f

__global__ __launch_bounds__(288)
void attn_group_mma()
{
    extern __shared__ float sm[];
    float* Ks = sm;                       // 257*68 (tf32-truncated values)
    float* Vs = sm + 257 * KSTR;          // 257*68 (fp32)
    float* Ps = sm + 2 * 257 * KSTR;      // 8 * 576
    float* Qm = Ps + 8 * 576;             // 64

    const int bhg  = blockIdx.x;
    const int g    = bhg & 7;
    const int h    = (bhg >> 3) & 15;
    const int b    = bhg >> 7;
    const int tid  = threadIdx.x;
    const int lane = tid & 31;
    const int w    = tid >> 5;
    const int brow = b * 2048 + g * GT;
    const float* qkvb = g_qkv + (size_t)brow * QKVN + h * 64;

    for (int idx = tid; idx < GT * 64; idx += 288) {
        int p = idx >> 6, d = idx & 63;
        const float* src = qkvb + (size_t)p * QKVN + d;
        Ks[p * KSTR + d] = __uint_as_float(f2tf32(src[1024]));
        Vs[p * KSTR + d] = src[2048];
    }
    if (tid < 64) {
        Ks[256 * KSTR + tid] = __uint_as_float(f2tf32(g_km[bhg * 64 + tid]));
        Vs[256 * KSTR + tid] = g_vm[bhg * 64 + tid];
        Qm[tid] = g_qm[bhg * 64 + tid];
    }
    __syncthreads();

    const int r  = lane >> 2;
    const int cq = lane & 3;
    const float QS = 0.125f * L2E;        // scores in log2 units

    if (w < 8) {
        float* myP = Ps + w * 576;

        for (int half = 0; half < 2; half++) {
            const int tile = half ? (15 - w) : w;
            const int i0 = tile * 16;

            uint32_t qf[8][4];
            const float* qg = qkvb + (size_t)i0 * QKVN;
#pragma unroll
            for (int kc = 0; kc < 8; kc++) {
                qf[kc][0] = f2tf32(QS * qg[(size_t)r * QKVN + kc * 8 + cq]);
                qf[kc][1] = f2tf32(QS * qg[(size_t)(r + 8) * QKVN + kc * 8 + cq]);
                qf[kc][2] = f2tf32(QS * qg[(size_t)r * QKVN + kc * 8 + cq + 4]);
                qf[kc][3] = f2tf32(QS * qg[(size_t)(r + 8) * QKVN + kc * 8 + cq + 4]);
            }

            float m0 = -1e30f, m1 = -1e30f, l0 = 0.f, l1 = 0.f;
            float oacc[8][4];
#pragma unroll
            for (int nt = 0; nt < 8; nt++)
#pragma unroll
                for (int q = 0; q < 4; q++) oacc[nt][q] = 0.f;

            const int nch = (i0 + 15) / 32 + 1;
            for (int c = 0; c < nch; c++) {
                const int j0 = c * 32;

                float s[4][4];
#pragma unroll
                for (int nt = 0; nt < 4; nt++) {
                    s[nt][0] = s[nt][1] = s[nt][2] = s[nt][3] = 0.f;
                    const float* kb = Ks + (j0 + nt * 8 + r) * KSTR;
#pragma unroll
                    for (int kc = 0; kc < 8; kc++) {
                        uint32_t b0 = __float_as_uint(kb[kc * 8 + cq]);
                        uint32_t b1 = __float_as_uint(kb[kc * 8 + cq + 4]);
                        mma_tf32(s[nt], qf[kc], b0, b1);
                    }
                }

                if (j0 + 31 > i0) {
#pragma unroll
                    for (int nt = 0; nt < 4; nt++) {
                        int j = j0 + nt * 8 + 2 * cq;
                        if (j     > i0 + r)     s[nt][0] = -1e30f;
                        if (j + 1 > i0 + r)     s[nt][1] = -1e30f;
                        if (j     > i0 + r + 8) s[nt][2] = -1e30f;
                        if (j + 1 > i0 + r + 8) s[nt][3] = -1e30f;
                    }
                }

                float cm0 = -1e30f, cm1 = -1e30f;
#pragma unroll
                for (int nt = 0; nt < 4; nt++) {
                    cm0 = fmaxf(cm0, fmaxf(s[nt][0], s[nt][1]));
                    cm1 = fmaxf(cm1, fmaxf(s[nt][2], s[nt][3]));
                }
                cm0 = fmaxf(cm0, __shfl_xor_sync(0xffffffffu, cm0, 1));
                cm0 = fmaxf(cm0, __shfl_xor_sync(0xffffffffu, cm0, 2));
                cm1 = fmaxf(cm1, __shfl_xor_sync(0xffffffffu, cm1, 1));
                cm1 = fmaxf(cm1, __shfl_xor_sync(0xffffffffu, cm1, 2));
                float mn0 = fmaxf(m0, cm0), mn1 = fmaxf(m1, cm1);
                float a0 = ex2p(m0 - mn0), a1 = ex2p(m1 - mn1);
                m0 = mn0; m1 = mn1;
                l0 *= a0; l1 *= a1;
#pragma unroll
                for (int nt = 0; nt < 8; nt++) {
                    oacc[nt][0] *= a0; oacc[nt][1] *= a0;
                    oacc[nt][2] *= a1; oacc[nt][3] *= a1;
                }
#pragma unroll
                for (int nt = 0; nt < 4; nt++) {
                    float p0 = ex2p(s[nt][0] - m0), p1 = ex2p(s[nt][1] - m0);
                    float p2 = ex2p(s[nt][2] - m1), p3 = ex2p(s[nt][3] - m1);
                    l0 += p0 + p1; l1 += p2 + p3;
                    int jl = nt * 8 + 2 * cq;
                    myP[r * 36 + jl]           = p0;
                    myP[r * 36 + jl + 1]       = p1;
                    myP[(r + 8) * 36 + jl]     = p2;
                    myP[(r + 8) * 36 + jl + 1] = p3;
                }
                __syncwarp();

#pragma unroll
                for (int kc = 0; kc < 4; kc++) {
                    uint32_t af[4];
                    af[0] = f2tf32(myP[r * 36 + kc * 8 + cq]);
                    af[1] = f2tf32(myP[(r + 8) * 36 + kc * 8 + cq]);
                    af[2] = f2tf32(myP[r * 36 + kc * 8 + cq + 4]);
                    af[3] = f2tf32(myP[(r + 8) * 36 + kc * 8 + cq + 4]);
                    const float* vb0 = Vs + (j0 + kc * 8 + cq) * KSTR;
                    const float* vb1 = Vs + (j0 + kc * 8 + cq + 4) * KSTR;
#pragma unroll
                    for (int nt = 0; nt < 8; nt++) {
                        uint32_t b0 = f2tf32(vb0[nt * 8 + r]);
                        uint32_t b1 = f2tf32(vb1[nt * 8 + r]);
                        mma_tf32(oacc[nt], af, b0, b1);
                    }
                }
                __syncwarp();
            }

            l0 += __shfl_xor_sync(0xffffffffu, l0, 1);
            l0 += __shfl_xor_sync(0xffffffffu, l0, 2);
            l1 += __shfl_xor_sync(0xffffffffu, l1, 1);
            l1 += __shfl_xor_sync(0xffffffffu, l1, 2);
            float inv0 = 1.f / l0, inv1 = 1.f / l1;
            float* o0row = g_xo + (size_t)(brow + i0 + r) * CDIM + h * 64;
            float* o1row = g_xo + (size_t)(brow + i0 + r + 8) * CDIM + h * 64;
#pragma unroll
            for (int nt = 0; nt < 8; nt++) {
                *(float2*)(o0row + nt * 8 + 2 * cq) =
                    make_float2(oacc[nt][0] * inv0, oacc[nt][1] * inv0);
                *(float2*)(o1row + nt * 8 + 2 * cq) =
                    make_float2(oacc[nt][2] * inv1, oacc[nt][3] * inv1);
            }
        }
    } else {
        // ---- warp 8: mean-token row (i = 256 attends j = 0..256)
        float s[9];
#pragma unroll
        for (int t = 0; t < 9; t++) s[t] = 0.f;
#pragma unroll
        for (int d0 = 0; d0 < 64; d0 += 16) {
            float q[16];
#pragma unroll
            for (int dd = 0; dd < 16; dd++) q[dd] = Qm[d0 + dd];
#pragma unroll
            for (int t = 0; t < 9; t++) {
                int j = lane + 32 * t;
                if (j < 257) {
                    const float* kb = Ks + j * KSTR + d0;
#pragma unroll
                    for (int dd = 0; dd < 16; dd++) s[t] += q[dd] * kb[dd];
                }
            }
        }
        float m = -1e30f;
#pragma unroll
        for (int t = 0; t < 9; t++) {
            int j = lane + 32 * t;
            if (j < 257) { s[t] *= QS; m = fmaxf(m, s[t]); }
        }
#pragma unroll
        for (int off = 16; off; off >>= 1)
            m = fmaxf(m, __shfl_xor_sync(0xffffffffu, m, off));
        float p[9]; float sum = 0.f;
#pragma unroll
        for (int t = 0; t < 9; t++) {
            int j = lane + 32 * t;
            p[t] = (j < 257) ? ex2p(s[t] - m) : 0.f;
            sum += p[t];
        }
#pragma unroll
        for (int off = 16; off; off >>= 1)
            sum += __shfl_xor_sync(0xffffffffu, sum, off);
        const float inv = 1.f / sum;
        float o0 = 0.f, o1 = 0.f;
        for (int t = 0; t < 9; t++) {
            int jmax = (t < 8) ? 32 : 1;
            for (int jj = 0; jj < jmax; jj++) {
                int j = 32 * t + jj;
                float pj = __shfl_sync(0xffffffffu, p[t], jj);
                o0 += pj * Vs[j * KSTR + lane];
                o1 += pj * Vs[j * KSTR + lane + 32];
            }
        }
        g_xm[bhg * 64 + lane]      = o0 * inv;
        g_xm[bhg * 64 + lane + 32] = o1 * inv;
    }
}

// ---------------------------------------------------------------------------
// Second attention over 7 groups (mean tokens), per (b,h). Emits yq/yk/yv.
// ---------------------------------------------------------------------------
__global__ void attn_cross_kernel(float* __restrict__ yq,
                                  float* __restrict__ yk,
                                  float* __restrict__ yv)
{
    __shared__ float Q[7][64], K[7][64], V[7][64], S[7][8];
    const int bh  = blockIdx.x;
    const int tid = threadIdx.x;

    const float* qb = g_qm + bh * 8 * 64;
    const float* kb = g_km + bh * 8 * 64;
    const float* vb = g_xm + bh * 8 * 64;
    for (int i = 0; i < 7; i++) {
        Q[i][tid] = qb[i * 64 + tid];
        K[i][tid] = kb[i * 64 + tid];
        V[i][tid] = vb[i * 64 + tid];
    }
    __syncthreads();

    if (tid < 49) {
        int i = tid / 7, j = tid % 7;
        float s = 0.f;
#pragma unroll
        for (int d = 0; d < 64; d++) s += Q[i][d] * K[j][d];
        S[i][j] = s * 0.125f;
    }
    __syncthreads();

    for (int i = 0; i < 7; i++) {
        float m = -3.0e38f;
        for (int j = 0; j <= i; j++) m = fmaxf(m, S[i][j]);
        float p[7], sum = 0.f;
        for (int j = 0; j <= i; j++) { p[j] = __expf(S[i][j] - m); sum += p[j]; }
        float o = 0.f;
        for (int j = 0; j <= i; j++) o += p[j] * V[j][tid];
        yv[(bh * 7 + i) * 64 + tid] = o / sum;
        yq[(bh * 7 + i) * 64 + tid] = Q[i][tid];
        yk[(bh * 7 + i) * 64 + tid] = K[i][tid];
    }
}

// ---------------------------------------------------------------------------
// kernel_launch
// ---------------------------------------------------------------------------
extern "C" void kernel_launch(void* const* d_in, const int* in_sizes, int n_in,
                              void* d_out, int out_size)
{
    const float* x      = (const float*)d_in[0];
    const float* W_attn = (const float*)d_in[1];
    const float* W_proj = (const float*)d_in[2];

    float* out = (float*)d_out;
    float* yq  = out + (size_t)MTOT * CDIM;
    float* yk  = yq + 8 * 16 * 7 * 64;
    float* yv  = yk + 8 * 16 * 7 * 64;

    float *qkv_p, *xo_p, *wat_p, *wpt_p;
    cudaGetSymbolAddress((void**)&qkv_p, g_qkv);
    cudaGetSymbolAddress((void**)&xo_p,  g_xo);
    cudaGetSymbolAddress((void**)&wat_p, g_wat);
    cudaGetSymbolAddress((void**)&wpt_p, g_wpt);

    const int ATTN_SMEM = ATTN_SMEM_F * (int)sizeof(float);   // 158,496 B
    cudaFuncSetAttribute(attn_group_mma,
                         cudaFuncAttributeMaxDynamicSharedMemorySize, ATTN_SMEM);
    cudaFuncSetAttribute(gemm_tf32,
                         cudaFuncAttributeMaxDynamicSharedMemorySize, GEMM_SMEM);

    // 0) transpose weights to [N,K] for ldmatrix-friendly B tiles
    transpose_k<<<dim3(QKVN / 32, CDIM / 32), dim3(32, 8)>>>(W_attn, wat_p,
                                                             CDIM, QKVN);
    transpose_k<<<dim3(CDIM / 32, CDIM / 32), dim3(32, 8)>>>(W_proj, wpt_p,
                                                             CDIM, CDIM);

    // 1) qkv = x @ W_attn   (TF32 tensor cores, ldmatrix fragments)
    gemm_tf32<<<dim3(QKVN / 128, MTOT / 128), 256, GEMM_SMEM>>>(
        x, wat_p, qkv_p, MTOT, QKVN, CDIM);
    // 2) per-(b,h,g) means
    mean_kernel<<<NMEAN / 256, 256>>>();
    // 3) group attention (tensor cores) -> g_xo, g_xm
    attn_group_mma<<<NBHG, 288, ATTN_SMEM>>>();
    // 4) cross-group attention -> yq/yk/yv
    attn_cross_kernel<<<128, 64>>>(yq, yk, yv);
    // 5) out = xo @ W_proj  (TF32 tensor cores, ldmatrix fragments)
    gemm_tf32<<<dim3(CDIM / 128, MTOT / 128), 256, GEMM_SMEM>>>(
        xo_p, wpt_p, out, MTOT, CDIM, CDIM);
}